// round 14
// baseline (speedup 1.0000x reference)
#include <cuda_runtime.h>
#include <cuda_fp16.h>
#include <cstdint>

#define N_NODES 100000
#define N_EDGES 3200000
#define IN_FEAT 256
#define OUT_FEAT 128

// Scratch (no dynamic alloc allowed)
__device__ int g_row_ptr[N_NODES + 1];
__device__ uint32_t g_wt[IN_FEAT * OUT_FEAT];           // W tf32(rna), [k][n]
__device__ __half g_femb16[(size_t)N_NODES * OUT_FEAT]; // fp16 shadow of femb

__device__ __forceinline__ uint32_t smem_u32(const void* p) {
    uint32_t a;
    asm("{ .reg .u64 t; cvta.to.shared.u64 t, %1; cvt.u32.u64 %0, t; }" : "=r"(a) : "l"(p));
    return a;
}
__device__ __forceinline__ uint32_t f2tf32(float f) {
    uint32_t r;
    asm("cvt.rna.tf32.f32 %0, %1;" : "=r"(r) : "f"(f));
    return r;
}
// cp.async 16B with src-size (0 => zero-fill, src not dereferenced)
__device__ __forceinline__ void cp16z(uint32_t dst, const void* src, int srcsize) {
    asm volatile("cp.async.cg.shared.global [%0], [%1], 16, %2;"
                 :: "r"(dst), "l"(src), "r"(srcsize));
}
__device__ __forceinline__ void cp16(uint32_t dst, const void* src) {
    asm volatile("cp.async.cg.shared.global [%0], [%1], 16;" :: "r"(dst), "l"(src));
}
#define CP_COMMIT() asm volatile("cp.async.commit_group;" ::: "memory")
#define CP_WAIT0()  asm volatile("cp.async.wait_group 0;" ::: "memory")
#define CP_WAIT1()  asm volatile("cp.async.wait_group 1;" ::: "memory")

// ---------------------------------------------------------------------------
// W tf32 convert (GEMM depends on this; tiny standalone launch).
// ---------------------------------------------------------------------------
__global__ void wt_kernel(const float* __restrict__ W) {
    int t = blockIdx.x * blockDim.x + threadIdx.x;
    if (t < IN_FEAT * OUT_FEAT) g_wt[t] = f2tf32(__ldg(W + t));
}

// ---------------------------------------------------------------------------
// GEMM v7b: v6 math (tf32 mma.sync m16n8k8, CTA 64x128, BK=16, 3-stage
// cp.async, 4 warps 2(M)x2(N), warp tile 32x64) + rowptr scan fused in the
// prologue + AIRTIGHT tail-wait ladder:
//   end of iter c needs stages 0..c+1 landed; issued = min(NCH, c+3)
//   => allowed outstanding = 1 for c <= NCH-3, 0 for c = NCH-2.
// (The WAIT1-only tail was a latent race — exposed in R13, fixed here.)
// ---------------------------------------------------------------------------
#define BM 64
#define BK 16
#define NCH (IN_FEAT / BK)       // 16
#define STAGES 3
#define AP 20
#define BP 136
#define AS_U32 (BM * AP)         // 1280 u32
#define BS_U32 (BK * BP)         // 2176 u32
#define STG_U32 (AS_U32 + BS_U32)             // 3456 u32 = 13824 B
#define SM_TOTAL (STAGES * STG_U32 * 4)       // 41472 B

__global__ void __launch_bounds__(128, 4) gemm_tf32_v7b(
    const float* __restrict__ A,       // [M, 256] fp32
    const int*   __restrict__ edge_row,
    float* __restrict__ C)             // [M, 128] fp32
{
    extern __shared__ uint32_t sm[];
    const uint32_t sb = smem_u32(sm);

    const int tid  = threadIdx.x;
    const int lane = tid & 31;
    const int wid  = tid >> 5;          // 0..3
    const int wm   = wid & 1;
    const int wn   = wid >> 1;
    const int row0 = blockIdx.x * BM;
    const int g    = lane >> 2;
    const int q    = lane & 3;

    float acc[2][8][4];
#pragma unroll
    for (int mi = 0; mi < 2; mi++)
#pragma unroll
        for (int ni = 0; ni < 8; ni++)
#pragma unroll
            for (int j = 0; j < 4; j++) acc[mi][ni][j] = 0.0f;

    const int ar0 = tid >> 2,          ac0 = (tid & 3) * 4;
    const int ar1 = (tid + 128) >> 2,  ac1 = ((tid + 128) & 3) * 4;
    const int asz0 = (row0 + ar0 < N_NODES) ? 16 : 0;
    const int asz1 = (row0 + ar1 < N_NODES) ? 16 : 0;
    const float* asrc0 = A + (size_t)min(row0 + ar0, N_NODES - 1) * IN_FEAT + ac0;
    const float* asrc1 = A + (size_t)min(row0 + ar1, N_NODES - 1) * IN_FEAT + ac1;
    int bk[4], bn[4];
#pragma unroll
    for (int i = 0; i < 4; i++) {
        int idx = tid + i * 128;
        bk[i] = idx >> 5;
        bn[i] = (idx & 31) * 4;
    }

#define ISSUE(c) do {                                                          \
    const int _st = (c) % STAGES;                                              \
    const int _k0 = (c) * BK;                                                  \
    uint32_t _ab = sb + (_st * STG_U32) * 4;                                   \
    uint32_t _bb = _ab + AS_U32 * 4;                                           \
    cp16z(_ab + (ar0 * AP + ac0) * 4, asrc0 + _k0, asz0);                      \
    cp16z(_ab + (ar1 * AP + ac1) * 4, asrc1 + _k0, asz1);                      \
    _Pragma("unroll")                                                          \
    for (int _i = 0; _i < 4; _i++)                                             \
        cp16(_bb + (bk[_i] * BP + bn[_i]) * 4,                                 \
             g_wt + (_k0 + bk[_i]) * OUT_FEAT + bn[_i]);                       \
    CP_COMMIT();                                                               \
} while (0)

    ISSUE(0);
    ISSUE(1);

    // ---- fused rowptr boundary scan, hidden under pipeline fill ----
    // thread gt covers edges [gt*16, gt*16+16); grid 1563*128 = 200064 >= 200000.
    {
        int gt = blockIdx.x * 128 + tid;
        int e0 = gt * 16;
        if (e0 < N_EDGES) {
            int prev = (e0 == 0) ? -1 : __ldg(edge_row + e0 - 1);
#pragma unroll
            for (int b = 0; b < 4; b++) {
                int4 cur = __ldg((const int4*)(edge_row + e0 + b * 4));
                for (int i = prev  + 1; i <= cur.x; i++) g_row_ptr[i] = e0 + b * 4 + 0;
                for (int i = cur.x + 1; i <= cur.y; i++) g_row_ptr[i] = e0 + b * 4 + 1;
                for (int i = cur.y + 1; i <= cur.z; i++) g_row_ptr[i] = e0 + b * 4 + 2;
                for (int i = cur.z + 1; i <= cur.w; i++) g_row_ptr[i] = e0 + b * 4 + 3;
                prev = cur.w;
            }
            if (e0 + 16 == N_EDGES)
                for (int i = prev + 1; i <= N_NODES; i++) g_row_ptr[i] = N_EDGES;
        }
    }

    CP_WAIT1();            // stage 0 landed (only groups 0,1 committed)
    __syncthreads();

    for (int c = 0; c < NCH; c++) {
        if (c + 2 < NCH) ISSUE(c + 2);

        const uint32_t* As = sm + (c % STAGES) * STG_U32;
        const uint32_t* Bs = As + AS_U32;

#pragma unroll
        for (int ks = 0; ks < BK; ks += 8) {
            uint32_t af[2][4];
#pragma unroll
            for (int mi = 0; mi < 2; mi++) {
                int m = wm * 32 + mi * 16 + g;
                af[mi][0] = As[m * AP + ks + q];
                af[mi][1] = As[(m + 8) * AP + ks + q];
                af[mi][2] = As[m * AP + ks + q + 4];
                af[mi][3] = As[(m + 8) * AP + ks + q + 4];
            }
            uint32_t bf[8][2];
#pragma unroll
            for (int ni = 0; ni < 8; ni++) {
                int n = wn * 64 + ni * 8 + g;
                bf[ni][0] = Bs[(ks + q) * BP + n];
                bf[ni][1] = Bs[(ks + q + 4) * BP + n];
            }
#pragma unroll
            for (int mi = 0; mi < 2; mi++)
#pragma unroll
                for (int ni = 0; ni < 8; ni++) {
                    asm volatile(
                        "mma.sync.aligned.m16n8k8.row.col.f32.tf32.tf32.f32 "
                        "{%0,%1,%2,%3}, {%4,%5,%6,%7}, {%8,%9}, {%0,%1,%2,%3};"
                        : "+f"(acc[mi][ni][0]), "+f"(acc[mi][ni][1]),
                          "+f"(acc[mi][ni][2]), "+f"(acc[mi][ni][3])
                        : "r"(af[mi][0]), "r"(af[mi][1]), "r"(af[mi][2]), "r"(af[mi][3]),
                          "r"(bf[ni][0]), "r"(bf[ni][1]));
                }
        }

        if (c + 1 < NCH) {
            if (c + 3 <= NCH) CP_WAIT1();   // c <= NCH-3: stage c+1 covered
            else              CP_WAIT0();   // c == NCH-2: group NCH-1 must drain
            __syncthreads();
        }
    }

    // Epilogue: fp32 to C, fp16 shadow to g_femb16.
#pragma unroll
    for (int mi = 0; mi < 2; mi++) {
        int r1 = row0 + wm * 32 + mi * 16 + g;
        int r2 = r1 + 8;
#pragma unroll
        for (int ni = 0; ni < 8; ni++) {
            int col = wn * 64 + ni * 8 + 2 * q;
            if (r1 < N_NODES) {
                *(float2*)(C + (size_t)r1 * OUT_FEAT + col) =
                    make_float2(acc[mi][ni][0], acc[mi][ni][1]);
                *(__half2*)(g_femb16 + (size_t)r1 * OUT_FEAT + col) =
                    __floats2half2_rn(acc[mi][ni][0], acc[mi][ni][1]);
            }
            if (r2 < N_NODES) {
                *(float2*)(C + (size_t)r2 * OUT_FEAT + col) =
                    make_float2(acc[mi][ni][2], acc[mi][ni][3]);
                *(__half2*)(g_femb16 + (size_t)r2 * OUT_FEAT + col) =
                    __floats2half2_rn(acc[mi][ni][2], acc[mi][ni][3]);
            }
        }
    }
}

// ---------------------------------------------------------------------------
// SpMM (frozen at measured ceiling, ~69.4us): one warp per node; lane owns 4
// cols (8B fp16 gather), fp32 accumulate; int4/float4 uniform edge loads.
// ---------------------------------------------------------------------------
__global__ __launch_bounds__(256) void spmm_kernel(
    const int* __restrict__ edge_col,
    const float* __restrict__ edge_val,
    float* __restrict__ x)
{
    int warp = (blockIdx.x * blockDim.x + threadIdx.x) >> 5;
    if (warp >= N_NODES) return;
    int lane = threadIdx.x & 31;

    int s = g_row_ptr[warp];
    int e = g_row_ptr[warp + 1];

    const __half2* fb = (const __half2*)g_femb16;   // [N * 64] half2

    float4 acc = make_float4(0.f, 0.f, 0.f, 0.f);
    int i = s;

    int head_end = min(e, (s + 3) & ~3);
    for (; i < head_end; i++) {
        int c = __ldg(edge_col + i);
        float v = __ldg(edge_val + i);
        uint2 u = *(const uint2*)(fb + (size_t)c * 64 + lane * 2);
        float2 fa = __half22float2(*(__half2*)&u.x);
        float2 fbv = __half22float2(*(__half2*)&u.y);
        acc.x = fmaf(v, fa.x, acc.x); acc.y = fmaf(v, fa.y, acc.y);
        acc.z = fmaf(v, fbv.x, acc.z); acc.w = fmaf(v, fbv.y, acc.w);
    }

    for (; i + 4 <= e; i += 4) {
        int4   c4 = __ldg((const int4*)(edge_col + i));
        float4 v4 = __ldg((const float4*)(edge_val + i));
        uint2 u0 = *(const uint2*)(fb + (size_t)c4.x * 64 + lane * 2);
        uint2 u1 = *(const uint2*)(fb + (size_t)c4.y * 64 + lane * 2);
        uint2 u2 = *(const uint2*)(fb + (size_t)c4.z * 64 + lane * 2);
        uint2 u3 = *(const uint2*)(fb + (size_t)c4.w * 64 + lane * 2);
        float2 f;
        f = __half22float2(*(__half2*)&u0.x); acc.x = fmaf(v4.x, f.x, acc.x); acc.y = fmaf(v4.x, f.y, acc.y);
        f = __half22float2(*(__half2*)&u0.y); acc.z = fmaf(v4.x, f.x, acc.z); acc.w = fmaf(v4.x, f.y, acc.w);
        f = __half22float2(*(__half2*)&u1.x); acc.x = fmaf(v4.y, f.x, acc.x); acc.y = fmaf(v4.y, f.y, acc.y);
        f = __half22float2(*(__half2*)&u1.y); acc.z = fmaf(v4.y, f.x, acc.z); acc.w = fmaf(v4.y, f.y, acc.w);
        f = __half22float2(*(__half2*)&u2.x); acc.x = fmaf(v4.z, f.x, acc.x); acc.y = fmaf(v4.z, f.y, acc.y);
        f = __half22float2(*(__half2*)&u2.y); acc.z = fmaf(v4.z, f.x, acc.z); acc.w = fmaf(v4.z, f.y, acc.w);
        f = __half22float2(*(__half2*)&u3.x); acc.x = fmaf(v4.w, f.x, acc.x); acc.y = fmaf(v4.w, f.y, acc.y);
        f = __half22float2(*(__half2*)&u3.y); acc.z = fmaf(v4.w, f.x, acc.z); acc.w = fmaf(v4.w, f.y, acc.w);
    }

    for (; i < e; i++) {
        int c = __ldg(edge_col + i);
        float v = __ldg(edge_val + i);
        uint2 u = *(const uint2*)(fb + (size_t)c * 64 + lane * 2);
        float2 fa = __half22float2(*(__half2*)&u.x);
        float2 fbv = __half22float2(*(__half2*)&u.y);
        acc.x = fmaf(v, fa.x, acc.x); acc.y = fmaf(v, fa.y, acc.y);
        acc.z = fmaf(v, fbv.x, acc.z); acc.w = fmaf(v, fbv.y, acc.w);
    }

    *(float4*)(x + (size_t)warp * OUT_FEAT + lane * 4) = acc;
}

// ---------------------------------------------------------------------------
extern "C" void kernel_launch(void* const* d_in, const int* in_sizes, int n_in,
                              void* d_out, int out_size)
{
    const float* feat     = (const float*)d_in[0];
    const int*   edge_row = (const int*)d_in[1];
    const int*   edge_col = (const int*)d_in[2];
    const float* edge_val = (const float*)d_in[3];
    const float* weight   = (const float*)d_in[4];

    float* femb = (float*)d_out;                              // [N, 128]
    float* x    = (float*)d_out + (size_t)N_NODES * OUT_FEAT; // [N, 128]

    cudaFuncSetAttribute(gemm_tf32_v7b, cudaFuncAttributeMaxDynamicSharedMemorySize, SM_TOTAL);

    wt_kernel<<<(IN_FEAT * OUT_FEAT + 127) / 128, 128>>>(weight);

    int gemm_blocks = (N_NODES + BM - 1) / BM;   // 1563
    gemm_tf32_v7b<<<gemm_blocks, 128, SM_TOTAL>>>(feat, edge_row, femb);

    int spmm_blocks = (N_NODES + 7) / 8;
    spmm_kernel<<<spmm_blocks, 256>>>(edge_col, edge_val, x);
}

// round 15
// speedup vs baseline: 1.0040x; 1.0040x over previous
#include <cuda_runtime.h>
#include <cuda_fp16.h>
#include <cstdint>

#define N_NODES 100000
#define N_EDGES 3200000
#define IN_FEAT 256
#define OUT_FEAT 128

// Scratch (no dynamic alloc allowed)
__device__ int g_row_ptr[N_NODES + 1];
__device__ uint32_t g_wt[IN_FEAT * OUT_FEAT];           // W tf32(rna), [k][n]
__device__ __half g_femb16[(size_t)N_NODES * OUT_FEAT]; // fp16 shadow of femb

__device__ __forceinline__ uint32_t smem_u32(const void* p) {
    uint32_t a;
    asm("{ .reg .u64 t; cvta.to.shared.u64 t, %1; cvt.u32.u64 %0, t; }" : "=r"(a) : "l"(p));
    return a;
}
__device__ __forceinline__ uint32_t f2tf32(float f) {
    uint32_t r;
    asm("cvt.rna.tf32.f32 %0, %1;" : "=r"(r) : "f"(f));
    return r;
}
// cp.async 16B with src-size (0 => zero-fill, src not dereferenced)
__device__ __forceinline__ void cp16z(uint32_t dst, const void* src, int srcsize) {
    asm volatile("cp.async.cg.shared.global [%0], [%1], 16, %2;"
                 :: "r"(dst), "l"(src), "r"(srcsize));
}
__device__ __forceinline__ void cp16(uint32_t dst, const void* src) {
    asm volatile("cp.async.cg.shared.global [%0], [%1], 16;" :: "r"(dst), "l"(src));
}
#define CP_COMMIT() asm volatile("cp.async.commit_group;" ::: "memory")
#define CP_WAIT0()  asm volatile("cp.async.wait_group 0;" ::: "memory")
#define CP_WAIT1()  asm volatile("cp.async.wait_group 1;" ::: "memory")

// ---------------------------------------------------------------------------
// Setup: rowptr boundary scan at 16 edges/thread (4 independent int4 loads
// issued up front) + W tf32 convert fused in the same launch.
// 200000 scan threads; grid 782x256 = 200192.
// ---------------------------------------------------------------------------
__device__ __forceinline__ void scan4(int prev, int4 cur, int e0) {
    for (int i = prev  + 1; i <= cur.x; i++) g_row_ptr[i] = e0 + 0;
    for (int i = cur.x + 1; i <= cur.y; i++) g_row_ptr[i] = e0 + 1;
    for (int i = cur.y + 1; i <= cur.z; i++) g_row_ptr[i] = e0 + 2;
    for (int i = cur.z + 1; i <= cur.w; i++) g_row_ptr[i] = e0 + 3;
}

__global__ void setup_kernel(const int* __restrict__ edge_row,
                             const float* __restrict__ W) {
    int t = blockIdx.x * blockDim.x + threadIdx.x;
    if (t < IN_FEAT * OUT_FEAT) g_wt[t] = f2tf32(__ldg(W + t));

    int e0 = t * 16;                      // N_EDGES % 16 == 0
    if (e0 >= N_EDGES) return;
    // 4 independent vector loads (MLP), plus one scalar (same line as neighbor)
    int4 c0 = __ldg((const int4*)(edge_row + e0 + 0));
    int4 c1 = __ldg((const int4*)(edge_row + e0 + 4));
    int4 c2 = __ldg((const int4*)(edge_row + e0 + 8));
    int4 c3 = __ldg((const int4*)(edge_row + e0 + 12));
    int prev = (e0 == 0) ? -1 : __ldg(edge_row + e0 - 1);

    scan4(prev, c0, e0);
    scan4(c0.w, c1, e0 + 4);
    scan4(c1.w, c2, e0 + 8);
    scan4(c2.w, c3, e0 + 12);

    if (e0 + 16 == N_EDGES)
        for (int i = c3.w + 1; i <= N_NODES; i++) g_row_ptr[i] = N_EDGES;
}

// ---------------------------------------------------------------------------
// GEMM v6c: R12-proven v6 (tf32 mma.sync m16n8k8, CTA 64x128, BK=16, 3-stage
// cp.async, 4 warps 2(M)x2(N), warp tile 32x64) + airtight tail-wait ladder
// (R13 proved the WAIT1-only tail is a real race; closed here).
// Epilogue: fp32 C + fp16 shadow.
// ---------------------------------------------------------------------------
#define BM 64
#define BK 16
#define NCH (IN_FEAT / BK)       // 16
#define STAGES 3
#define AP 20
#define BP 136
#define AS_U32 (BM * AP)         // 1280 u32
#define BS_U32 (BK * BP)         // 2176 u32
#define STG_U32 (AS_U32 + BS_U32)             // 3456 u32 = 13824 B
#define SM_TOTAL (STAGES * STG_U32 * 4)       // 41472 B

__global__ void __launch_bounds__(128, 4) gemm_tf32_v6c(
    const float* __restrict__ A,   // [M, 256] fp32
    float* __restrict__ C)         // [M, 128] fp32
{
    extern __shared__ uint32_t sm[];
    const uint32_t sb = smem_u32(sm);

    const int tid  = threadIdx.x;
    const int lane = tid & 31;
    const int wid  = tid >> 5;          // 0..3
    const int wm   = wid & 1;
    const int wn   = wid >> 1;
    const int row0 = blockIdx.x * BM;
    const int g    = lane >> 2;
    const int q    = lane & 3;

    float acc[2][8][4];
#pragma unroll
    for (int mi = 0; mi < 2; mi++)
#pragma unroll
        for (int ni = 0; ni < 8; ni++)
#pragma unroll
            for (int j = 0; j < 4; j++) acc[mi][ni][j] = 0.0f;

    const int ar0 = tid >> 2,          ac0 = (tid & 3) * 4;
    const int ar1 = (tid + 128) >> 2,  ac1 = ((tid + 128) & 3) * 4;
    const int asz0 = (row0 + ar0 < N_NODES) ? 16 : 0;
    const int asz1 = (row0 + ar1 < N_NODES) ? 16 : 0;
    const float* asrc0 = A + (size_t)min(row0 + ar0, N_NODES - 1) * IN_FEAT + ac0;
    const float* asrc1 = A + (size_t)min(row0 + ar1, N_NODES - 1) * IN_FEAT + ac1;
    int bk[4], bn[4];
#pragma unroll
    for (int i = 0; i < 4; i++) {
        int idx = tid + i * 128;
        bk[i] = idx >> 5;
        bn[i] = (idx & 31) * 4;
    }

#define ISSUE(c) do {                                                          \
    const int _st = (c) % STAGES;                                              \
    const int _k0 = (c) * BK;                                                  \
    uint32_t _ab = sb + (_st * STG_U32) * 4;                                   \
    uint32_t _bb = _ab + AS_U32 * 4;                                           \
    cp16z(_ab + (ar0 * AP + ac0) * 4, asrc0 + _k0, asz0);                      \
    cp16z(_ab + (ar1 * AP + ac1) * 4, asrc1 + _k0, asz1);                      \
    _Pragma("unroll")                                                          \
    for (int _i = 0; _i < 4; _i++)                                             \
        cp16(_bb + (bk[_i] * BP + bn[_i]) * 4,                                 \
             g_wt + (_k0 + bk[_i]) * OUT_FEAT + bn[_i]);                       \
    CP_COMMIT();                                                               \
} while (0)

    ISSUE(0);
    ISSUE(1);
    CP_WAIT1();            // stage 0 landed (only groups 0,1 committed)
    __syncthreads();

    for (int c = 0; c < NCH; c++) {
        if (c + 2 < NCH) ISSUE(c + 2);

        const uint32_t* As = sm + (c % STAGES) * STG_U32;
        const uint32_t* Bs = As + AS_U32;

#pragma unroll
        for (int ks = 0; ks < BK; ks += 8) {
            uint32_t af[2][4];
#pragma unroll
            for (int mi = 0; mi < 2; mi++) {
                int m = wm * 32 + mi * 16 + g;
                af[mi][0] = As[m * AP + ks + q];
                af[mi][1] = As[(m + 8) * AP + ks + q];
                af[mi][2] = As[m * AP + ks + q + 4];
                af[mi][3] = As[(m + 8) * AP + ks + q + 4];
            }
            uint32_t bf[8][2];
#pragma unroll
            for (int ni = 0; ni < 8; ni++) {
                int n = wn * 64 + ni * 8 + g;
                bf[ni][0] = Bs[(ks + q) * BP + n];
                bf[ni][1] = Bs[(ks + q + 4) * BP + n];
            }
#pragma unroll
            for (int mi = 0; mi < 2; mi++)
#pragma unroll
                for (int ni = 0; ni < 8; ni++) {
                    asm volatile(
                        "mma.sync.aligned.m16n8k8.row.col.f32.tf32.tf32.f32 "
                        "{%0,%1,%2,%3}, {%4,%5,%6,%7}, {%8,%9}, {%0,%1,%2,%3};"
                        : "+f"(acc[mi][ni][0]), "+f"(acc[mi][ni][1]),
                          "+f"(acc[mi][ni][2]), "+f"(acc[mi][ni][3])
                        : "r"(af[mi][0]), "r"(af[mi][1]), "r"(af[mi][2]), "r"(af[mi][3]),
                          "r"(bf[ni][0]), "r"(bf[ni][1]));
                }
        }

        if (c + 1 < NCH) {
            if (c + 3 <= NCH) CP_WAIT1();   // c <= NCH-3: stage c+1 covered
            else              CP_WAIT0();   // c == NCH-2: last group must drain
            __syncthreads();
        }
    }

    // Epilogue: fp32 to C, fp16 shadow to g_femb16.
#pragma unroll
    for (int mi = 0; mi < 2; mi++) {
        int r1 = row0 + wm * 32 + mi * 16 + g;
        int r2 = r1 + 8;
#pragma unroll
        for (int ni = 0; ni < 8; ni++) {
            int col = wn * 64 + ni * 8 + 2 * q;
            if (r1 < N_NODES) {
                *(float2*)(C + (size_t)r1 * OUT_FEAT + col) =
                    make_float2(acc[mi][ni][0], acc[mi][ni][1]);
                *(__half2*)(g_femb16 + (size_t)r1 * OUT_FEAT + col) =
                    __floats2half2_rn(acc[mi][ni][0], acc[mi][ni][1]);
            }
            if (r2 < N_NODES) {
                *(float2*)(C + (size_t)r2 * OUT_FEAT + col) =
                    make_float2(acc[mi][ni][2], acc[mi][ni][3]);
                *(__half2*)(g_femb16 + (size_t)r2 * OUT_FEAT + col) =
                    __floats2half2_rn(acc[mi][ni][2], acc[mi][ni][3]);
            }
        }
    }
}

// ---------------------------------------------------------------------------
// SpMM (frozen at measured LTS ceiling, ~69.4us): one warp per node; lane owns
// 4 cols (8B fp16 gather), fp32 accumulate; int4/float4 uniform edge loads.
// ---------------------------------------------------------------------------
__global__ __launch_bounds__(256) void spmm_kernel(
    const int* __restrict__ edge_col,
    const float* __restrict__ edge_val,
    float* __restrict__ x)
{
    int warp = (blockIdx.x * blockDim.x + threadIdx.x) >> 5;
    if (warp >= N_NODES) return;
    int lane = threadIdx.x & 31;

    int s = g_row_ptr[warp];
    int e = g_row_ptr[warp + 1];

    const __half2* fb = (const __half2*)g_femb16;   // [N * 64] half2

    float4 acc = make_float4(0.f, 0.f, 0.f, 0.f);
    int i = s;

    int head_end = min(e, (s + 3) & ~3);
    for (; i < head_end; i++) {
        int c = __ldg(edge_col + i);
        float v = __ldg(edge_val + i);
        uint2 u = *(const uint2*)(fb + (size_t)c * 64 + lane * 2);
        float2 fa = __half22float2(*(__half2*)&u.x);
        float2 fbv = __half22float2(*(__half2*)&u.y);
        acc.x = fmaf(v, fa.x, acc.x); acc.y = fmaf(v, fa.y, acc.y);
        acc.z = fmaf(v, fbv.x, acc.z); acc.w = fmaf(v, fbv.y, acc.w);
    }

    for (; i + 4 <= e; i += 4) {
        int4   c4 = __ldg((const int4*)(edge_col + i));
        float4 v4 = __ldg((const float4*)(edge_val + i));
        uint2 u0 = *(const uint2*)(fb + (size_t)c4.x * 64 + lane * 2);
        uint2 u1 = *(const uint2*)(fb + (size_t)c4.y * 64 + lane * 2);
        uint2 u2 = *(const uint2*)(fb + (size_t)c4.z * 64 + lane * 2);
        uint2 u3 = *(const uint2*)(fb + (size_t)c4.w * 64 + lane * 2);
        float2 f;
        f = __half22float2(*(__half2*)&u0.x); acc.x = fmaf(v4.x, f.x, acc.x); acc.y = fmaf(v4.x, f.y, acc.y);
        f = __half22float2(*(__half2*)&u0.y); acc.z = fmaf(v4.x, f.x, acc.z); acc.w = fmaf(v4.x, f.y, acc.w);
        f = __half22float2(*(__half2*)&u1.x); acc.x = fmaf(v4.y, f.x, acc.x); acc.y = fmaf(v4.y, f.y, acc.y);
        f = __half22float2(*(__half2*)&u1.y); acc.z = fmaf(v4.y, f.x, acc.z); acc.w = fmaf(v4.y, f.y, acc.w);
        f = __half22float2(*(__half2*)&u2.x); acc.x = fmaf(v4.z, f.x, acc.x); acc.y = fmaf(v4.z, f.y, acc.y);
        f = __half22float2(*(__half2*)&u2.y); acc.z = fmaf(v4.z, f.x, acc.z); acc.w = fmaf(v4.z, f.y, acc.w);
        f = __half22float2(*(__half2*)&u3.x); acc.x = fmaf(v4.w, f.x, acc.x); acc.y = fmaf(v4.w, f.y, acc.y);
        f = __half22float2(*(__half2*)&u3.y); acc.z = fmaf(v4.w, f.x, acc.z); acc.w = fmaf(v4.w, f.y, acc.w);
    }

    for (; i < e; i++) {
        int c = __ldg(edge_col + i);
        float v = __ldg(edge_val + i);
        uint2 u = *(const uint2*)(fb + (size_t)c * 64 + lane * 2);
        float2 fa = __half22float2(*(__half2*)&u.x);
        float2 fbv = __half22float2(*(__half2*)&u.y);
        acc.x = fmaf(v, fa.x, acc.x); acc.y = fmaf(v, fa.y, acc.y);
        acc.z = fmaf(v, fbv.x, acc.z); acc.w = fmaf(v, fbv.y, acc.w);
    }

    *(float4*)(x + (size_t)warp * OUT_FEAT + lane * 4) = acc;
}

// ---------------------------------------------------------------------------
extern "C" void kernel_launch(void* const* d_in, const int* in_sizes, int n_in,
                              void* d_out, int out_size)
{
    const float* feat     = (const float*)d_in[0];
    const int*   edge_row = (const int*)d_in[1];
    const int*   edge_col = (const int*)d_in[2];
    const float* edge_val = (const float*)d_in[3];
    const float* weight   = (const float*)d_in[4];

    float* femb = (float*)d_out;                              // [N, 128]
    float* x    = (float*)d_out + (size_t)N_NODES * OUT_FEAT; // [N, 128]

    cudaFuncSetAttribute(gemm_tf32_v6c, cudaFuncAttributeMaxDynamicSharedMemorySize, SM_TOTAL);

    setup_kernel<<<(N_EDGES / 16 + 255) / 256, 256>>>(edge_row, weight);

    int gemm_blocks = (N_NODES + BM - 1) / BM;   // 1563
    gemm_tf32_v6c<<<gemm_blocks, 128, SM_TOTAL>>>(feat, femb);

    int spmm_blocks = (N_NODES + 7) / 8;
    spmm_kernel<<<spmm_blocks, 256>>>(edge_col, edge_val, x);
}

// round 16
// speedup vs baseline: 1.0170x; 1.0130x over previous
#include <cuda_runtime.h>
#include <cuda_fp16.h>
#include <cstdint>

#define N_NODES 100000
#define N_EDGES 3200000
#define IN_FEAT 256
#define OUT_FEAT 128

// Scratch (no dynamic alloc allowed)
__device__ int g_row_ptr[N_NODES + 1];
__device__ uint32_t g_wt[IN_FEAT * OUT_FEAT];           // W tf32(rna), [k][n]
__device__ __half g_femb16[(size_t)N_NODES * OUT_FEAT]; // fp16 shadow of femb

__device__ __forceinline__ uint32_t smem_u32(const void* p) {
    uint32_t a;
    asm("{ .reg .u64 t; cvta.to.shared.u64 t, %1; cvt.u32.u64 %0, t; }" : "=r"(a) : "l"(p));
    return a;
}
__device__ __forceinline__ uint32_t f2tf32(float f) {
    uint32_t r;
    asm("cvt.rna.tf32.f32 %0, %1;" : "=r"(r) : "f"(f));
    return r;
}
// cp.async 16B with src-size (0 => zero-fill, src not dereferenced)
__device__ __forceinline__ void cp16z(uint32_t dst, const void* src, int srcsize) {
    asm volatile("cp.async.cg.shared.global [%0], [%1], 16, %2;"
                 :: "r"(dst), "l"(src), "r"(srcsize));
}
__device__ __forceinline__ void cp16(uint32_t dst, const void* src) {
    asm volatile("cp.async.cg.shared.global [%0], [%1], 16;" :: "r"(dst), "l"(src));
}
#define CP_COMMIT() asm volatile("cp.async.commit_group;" ::: "memory")
#define CP_WAIT0()  asm volatile("cp.async.wait_group 0;" ::: "memory")
#define CP_WAIT1()  asm volatile("cp.async.wait_group 1;" ::: "memory")

// ---------------------------------------------------------------------------
// Setup (PDL primary): wt convert first, then TRIGGER (releases the GEMM's
// grid-dependency wait), then the rowptr 4-edge boundary scan — which now
// overlaps with the GEMM. Grid: 3125 x 256 (R12-proven scan config).
// ---------------------------------------------------------------------------
__global__ void setup_kernel(const int* __restrict__ edge_row,
                             const float* __restrict__ W) {
    int t = blockIdx.x * blockDim.x + threadIdx.x;
    if (t < IN_FEAT * OUT_FEAT) g_wt[t] = f2tf32(__ldg(W + t));

    // All blocks trigger; fires once every block has. g_wt writes above are
    // visible to the secondary grid after its cudaGridDependencySynchronize().
    cudaTriggerProgrammaticLaunchCompletion();

    int e0 = t * 4;                      // N_EDGES % 4 == 0
    if (e0 >= N_EDGES) return;
    int4 cur = __ldg((const int4*)(edge_row + e0));
    int prev = (e0 == 0) ? -1 : __ldg(edge_row + e0 - 1);

    for (int i = prev  + 1; i <= cur.x; i++) g_row_ptr[i] = e0 + 0;
    for (int i = cur.x + 1; i <= cur.y; i++) g_row_ptr[i] = e0 + 1;
    for (int i = cur.y + 1; i <= cur.z; i++) g_row_ptr[i] = e0 + 2;
    for (int i = cur.z + 1; i <= cur.w; i++) g_row_ptr[i] = e0 + 3;

    if (e0 + 4 == N_EDGES)
        for (int i = cur.w + 1; i <= N_NODES; i++) g_row_ptr[i] = N_EDGES;
}

// ---------------------------------------------------------------------------
// GEMM v8 (PDL secondary): R12-proven v6 math (tf32 mma.sync m16n8k8, CTA
// 64x128, BK=16, 3-stage cp.async, 4 warps 2(M)x2(N), warp tile 32x64) +
// airtight tail-wait ladder (R13 race closed) + grid-dependency sync before
// the first g_wt read. Epilogue: fp32 C + fp16 shadow.
// ---------------------------------------------------------------------------
#define BM 64
#define BK 16
#define NCH (IN_FEAT / BK)       // 16
#define STAGES 3
#define AP 20
#define BP 136
#define AS_U32 (BM * AP)         // 1280 u32
#define BS_U32 (BK * BP)         // 2176 u32
#define STG_U32 (AS_U32 + BS_U32)             // 3456 u32 = 13824 B
#define SM_TOTAL (STAGES * STG_U32 * 4)       // 41472 B

__global__ void __launch_bounds__(128, 4) gemm_tf32_v8(
    const float* __restrict__ A,   // [M, 256] fp32
    float* __restrict__ C)         // [M, 128] fp32
{
    extern __shared__ uint32_t sm[];
    const uint32_t sb = smem_u32(sm);

    const int tid  = threadIdx.x;
    const int lane = tid & 31;
    const int wid  = tid >> 5;          // 0..3
    const int wm   = wid & 1;
    const int wn   = wid >> 1;
    const int row0 = blockIdx.x * BM;
    const int g    = lane >> 2;
    const int q    = lane & 3;

    float acc[2][8][4];
#pragma unroll
    for (int mi = 0; mi < 2; mi++)
#pragma unroll
        for (int ni = 0; ni < 8; ni++)
#pragma unroll
            for (int j = 0; j < 4; j++) acc[mi][ni][j] = 0.0f;

    const int ar0 = tid >> 2,          ac0 = (tid & 3) * 4;
    const int ar1 = (tid + 128) >> 2,  ac1 = ((tid + 128) & 3) * 4;
    const int asz0 = (row0 + ar0 < N_NODES) ? 16 : 0;
    const int asz1 = (row0 + ar1 < N_NODES) ? 16 : 0;
    const float* asrc0 = A + (size_t)min(row0 + ar0, N_NODES - 1) * IN_FEAT + ac0;
    const float* asrc1 = A + (size_t)min(row0 + ar1, N_NODES - 1) * IN_FEAT + ac1;
    int bk[4], bn[4];
#pragma unroll
    for (int i = 0; i < 4; i++) {
        int idx = tid + i * 128;
        bk[i] = idx >> 5;
        bn[i] = (idx & 31) * 4;
    }

    // Wait for the primary (setup) grid's trigger: g_wt is ready after this.
    cudaGridDependencySynchronize();

#define ISSUE(c) do {                                                          \
    const int _st = (c) % STAGES;                                              \
    const int _k0 = (c) * BK;                                                  \
    uint32_t _ab = sb + (_st * STG_U32) * 4;                                   \
    uint32_t _bb = _ab + AS_U32 * 4;                                           \
    cp16z(_ab + (ar0 * AP + ac0) * 4, asrc0 + _k0, asz0);                      \
    cp16z(_ab + (ar1 * AP + ac1) * 4, asrc1 + _k0, asz1);                      \
    _Pragma("unroll")                                                          \
    for (int _i = 0; _i < 4; _i++)                                             \
        cp16(_bb + (bk[_i] * BP + bn[_i]) * 4,                                 \
             g_wt + (_k0 + bk[_i]) * OUT_FEAT + bn[_i]);                       \
    CP_COMMIT();                                                               \
} while (0)

    ISSUE(0);
    ISSUE(1);
    CP_WAIT1();            // stage 0 landed (only groups 0,1 committed)
    __syncthreads();

    for (int c = 0; c < NCH; c++) {
        if (c + 2 < NCH) ISSUE(c + 2);

        const uint32_t* As = sm + (c % STAGES) * STG_U32;
        const uint32_t* Bs = As + AS_U32;

#pragma unroll
        for (int ks = 0; ks < BK; ks += 8) {
            uint32_t af[2][4];
#pragma unroll
            for (int mi = 0; mi < 2; mi++) {
                int m = wm * 32 + mi * 16 + g;
                af[mi][0] = As[m * AP + ks + q];
                af[mi][1] = As[(m + 8) * AP + ks + q];
                af[mi][2] = As[m * AP + ks + q + 4];
                af[mi][3] = As[(m + 8) * AP + ks + q + 4];
            }
            uint32_t bf[8][2];
#pragma unroll
            for (int ni = 0; ni < 8; ni++) {
                int n = wn * 64 + ni * 8 + g;
                bf[ni][0] = Bs[(ks + q) * BP + n];
                bf[ni][1] = Bs[(ks + q + 4) * BP + n];
            }
#pragma unroll
            for (int mi = 0; mi < 2; mi++)
#pragma unroll
                for (int ni = 0; ni < 8; ni++) {
                    asm volatile(
                        "mma.sync.aligned.m16n8k8.row.col.f32.tf32.tf32.f32 "
                        "{%0,%1,%2,%3}, {%4,%5,%6,%7}, {%8,%9}, {%0,%1,%2,%3};"
                        : "+f"(acc[mi][ni][0]), "+f"(acc[mi][ni][1]),
                          "+f"(acc[mi][ni][2]), "+f"(acc[mi][ni][3])
                        : "r"(af[mi][0]), "r"(af[mi][1]), "r"(af[mi][2]), "r"(af[mi][3]),
                          "r"(bf[ni][0]), "r"(bf[ni][1]));
                }
        }

        if (c + 1 < NCH) {
            if (c + 3 <= NCH) CP_WAIT1();   // c <= NCH-3: stage c+1 covered
            else              CP_WAIT0();   // c == NCH-2: last group must drain
            __syncthreads();
        }
    }

    // Epilogue: fp32 to C, fp16 shadow to g_femb16.
#pragma unroll
    for (int mi = 0; mi < 2; mi++) {
        int r1 = row0 + wm * 32 + mi * 16 + g;
        int r2 = r1 + 8;
#pragma unroll
        for (int ni = 0; ni < 8; ni++) {
            int col = wn * 64 + ni * 8 + 2 * q;
            if (r1 < N_NODES) {
                *(float2*)(C + (size_t)r1 * OUT_FEAT + col) =
                    make_float2(acc[mi][ni][0], acc[mi][ni][1]);
                *(__half2*)(g_femb16 + (size_t)r1 * OUT_FEAT + col) =
                    __floats2half2_rn(acc[mi][ni][0], acc[mi][ni][1]);
            }
            if (r2 < N_NODES) {
                *(float2*)(C + (size_t)r2 * OUT_FEAT + col) =
                    make_float2(acc[mi][ni][2], acc[mi][ni][3]);
                *(__half2*)(g_femb16 + (size_t)r2 * OUT_FEAT + col) =
                    __floats2half2_rn(acc[mi][ni][2], acc[mi][ni][3]);
            }
        }
    }
}

// ---------------------------------------------------------------------------
// SpMM (frozen at measured LTS ceiling, ~69.4us): one warp per node; lane owns
// 4 cols (8B fp16 gather), fp32 accumulate; int4/float4 uniform edge loads.
// ---------------------------------------------------------------------------
__global__ __launch_bounds__(256) void spmm_kernel(
    const int* __restrict__ edge_col,
    const float* __restrict__ edge_val,
    float* __restrict__ x)
{
    int warp = (blockIdx.x * blockDim.x + threadIdx.x) >> 5;
    if (warp >= N_NODES) return;
    int lane = threadIdx.x & 31;

    int s = g_row_ptr[warp];
    int e = g_row_ptr[warp + 1];

    const __half2* fb = (const __half2*)g_femb16;   // [N * 64] half2

    float4 acc = make_float4(0.f, 0.f, 0.f, 0.f);
    int i = s;

    int head_end = min(e, (s + 3) & ~3);
    for (; i < head_end; i++) {
        int c = __ldg(edge_col + i);
        float v = __ldg(edge_val + i);
        uint2 u = *(const uint2*)(fb + (size_t)c * 64 + lane * 2);
        float2 fa = __half22float2(*(__half2*)&u.x);
        float2 fbv = __half22float2(*(__half2*)&u.y);
        acc.x = fmaf(v, fa.x, acc.x); acc.y = fmaf(v, fa.y, acc.y);
        acc.z = fmaf(v, fbv.x, acc.z); acc.w = fmaf(v, fbv.y, acc.w);
    }

    for (; i + 4 <= e; i += 4) {
        int4   c4 = __ldg((const int4*)(edge_col + i));
        float4 v4 = __ldg((const float4*)(edge_val + i));
        uint2 u0 = *(const uint2*)(fb + (size_t)c4.x * 64 + lane * 2);
        uint2 u1 = *(const uint2*)(fb + (size_t)c4.y * 64 + lane * 2);
        uint2 u2 = *(const uint2*)(fb + (size_t)c4.z * 64 + lane * 2);
        uint2 u3 = *(const uint2*)(fb + (size_t)c4.w * 64 + lane * 2);
        float2 f;
        f = __half22float2(*(__half2*)&u0.x); acc.x = fmaf(v4.x, f.x, acc.x); acc.y = fmaf(v4.x, f.y, acc.y);
        f = __half22float2(*(__half2*)&u0.y); acc.z = fmaf(v4.x, f.x, acc.z); acc.w = fmaf(v4.x, f.y, acc.w);
        f = __half22float2(*(__half2*)&u1.x); acc.x = fmaf(v4.y, f.x, acc.x); acc.y = fmaf(v4.y, f.y, acc.y);
        f = __half22float2(*(__half2*)&u1.y); acc.z = fmaf(v4.y, f.x, acc.z); acc.w = fmaf(v4.y, f.y, acc.w);
        f = __half22float2(*(__half2*)&u2.x); acc.x = fmaf(v4.z, f.x, acc.x); acc.y = fmaf(v4.z, f.y, acc.y);
        f = __half22float2(*(__half2*)&u2.y); acc.z = fmaf(v4.z, f.x, acc.z); acc.w = fmaf(v4.z, f.y, acc.w);
        f = __half22float2(*(__half2*)&u3.x); acc.x = fmaf(v4.w, f.x, acc.x); acc.y = fmaf(v4.w, f.y, acc.y);
        f = __half22float2(*(__half2*)&u3.y); acc.z = fmaf(v4.w, f.x, acc.z); acc.w = fmaf(v4.w, f.y, acc.w);
    }

    for (; i < e; i++) {
        int c = __ldg(edge_col + i);
        float v = __ldg(edge_val + i);
        uint2 u = *(const uint2*)(fb + (size_t)c * 64 + lane * 2);
        float2 fa = __half22float2(*(__half2*)&u.x);
        float2 fbv = __half22float2(*(__half2*)&u.y);
        acc.x = fmaf(v, fa.x, acc.x); acc.y = fmaf(v, fa.y, acc.y);
        acc.z = fmaf(v, fbv.x, acc.z); acc.w = fmaf(v, fbv.y, acc.w);
    }

    *(float4*)(x + (size_t)warp * OUT_FEAT + lane * 4) = acc;
}

// ---------------------------------------------------------------------------
extern "C" void kernel_launch(void* const* d_in, const int* in_sizes, int n_in,
                              void* d_out, int out_size)
{
    const float* feat     = (const float*)d_in[0];
    const int*   edge_row = (const int*)d_in[1];
    const int*   edge_col = (const int*)d_in[2];
    const float* edge_val = (const float*)d_in[3];
    const float* weight   = (const float*)d_in[4];

    float* femb = (float*)d_out;                              // [N, 128]
    float* x    = (float*)d_out + (size_t)N_NODES * OUT_FEAT; // [N, 128]

    cudaFuncSetAttribute(gemm_tf32_v8, cudaFuncAttributeMaxDynamicSharedMemorySize, SM_TOTAL);

    // Primary: wt convert (trigger) + rowptr scan (overlapped with GEMM).
    setup_kernel<<<(N_EDGES / 4 + 255) / 256, 256>>>(edge_row, weight);

    // Secondary: GEMM with programmatic dependent launch — starts during the
    // setup kernel; cudaGridDependencySynchronize() gates the g_wt reads.
    {
        cudaLaunchConfig_t cfg = {};
        cfg.gridDim = dim3((N_NODES + BM - 1) / BM);   // 1563
        cfg.blockDim = dim3(128);
        cfg.dynamicSmemBytes = SM_TOTAL;
        cfg.stream = 0;
        cudaLaunchAttribute attr[1];
        attr[0].id = cudaLaunchAttributeProgrammaticStreamSerialization;
        attr[0].val.programmaticStreamSerializationAllowed = 1;
        cfg.attrs = attr;
        cfg.numAttrs = 1;
        cudaLaunchKernelEx(&cfg, gemm_tf32_v8, feat, femb);
    }

    // SpMM: stream-ordered after both grids (PDL preserves downstream order).
    int spmm_blocks = (N_NODES + 7) / 8;
    spmm_kernel<<<spmm_blocks, 256>>>(edge_col, edge_val, x);
}

// round 17
// speedup vs baseline: 1.0472x; 1.0296x over previous
#include <cuda_runtime.h>
#include <cuda_fp16.h>
#include <cstdint>

#define N_NODES 100000
#define N_EDGES 3200000
#define IN_FEAT 256
#define OUT_FEAT 128

// Scratch (no dynamic alloc allowed)
__device__ int g_row_ptr[N_NODES + 1];
__device__ uint32_t g_wt[IN_FEAT * OUT_FEAT];           // W tf32(rna), [k][n]
__device__ __half g_femb16[(size_t)N_NODES * OUT_FEAT]; // fp16 shadow of femb

__device__ __forceinline__ uint32_t smem_u32(const void* p) {
    uint32_t a;
    asm("{ .reg .u64 t; cvta.to.shared.u64 t, %1; cvt.u32.u64 %0, t; }" : "=r"(a) : "l"(p));
    return a;
}
__device__ __forceinline__ uint32_t f2tf32(float f) {
    uint32_t r;
    asm("cvt.rna.tf32.f32 %0, %1;" : "=r"(r) : "f"(f));
    return r;
}
// cp.async 16B with src-size (0 => zero-fill, src not dereferenced)
__device__ __forceinline__ void cp16z(uint32_t dst, const void* src, int srcsize) {
    asm volatile("cp.async.cg.shared.global [%0], [%1], 16, %2;"
                 :: "r"(dst), "l"(src), "r"(srcsize));
}
__device__ __forceinline__ void cp16(uint32_t dst, const void* src) {
    asm volatile("cp.async.cg.shared.global [%0], [%1], 16;" :: "r"(dst), "l"(src));
}
#define CP_COMMIT() asm volatile("cp.async.commit_group;" ::: "memory")
#define CP_WAIT0()  asm volatile("cp.async.wait_group 0;" ::: "memory")
#define CP_WAIT1()  asm volatile("cp.async.wait_group 1;" ::: "memory")

// ---------------------------------------------------------------------------
// 1) wt convert — tiny single-wave grid so its PDL trigger fires early.
// ---------------------------------------------------------------------------
__global__ void wt_kernel(const float* __restrict__ W) {
    int t = blockIdx.x * blockDim.x + threadIdx.x;
    if (t < IN_FEAT * OUT_FEAT) g_wt[t] = f2tf32(__ldg(W + t));
    cudaTriggerProgrammaticLaunchCompletion();
}

// ---------------------------------------------------------------------------
// 3) rowptr scan (R12-proven 4-edge/thread config) — PDL secondary of the
// GEMM, but reads NOTHING the GEMM writes, so it skips the grid sync and
// runs concurrently with the GEMM's tail.
// ---------------------------------------------------------------------------
__global__ void rowptr_kernel(const int* __restrict__ edge_row) {
    int t = blockIdx.x * blockDim.x + threadIdx.x;
    int e0 = t * 4;                      // N_EDGES % 4 == 0
    if (e0 >= N_EDGES) return;
    int4 cur = __ldg((const int4*)(edge_row + e0));
    int prev = (e0 == 0) ? -1 : __ldg(edge_row + e0 - 1);

    for (int i = prev  + 1; i <= cur.x; i++) g_row_ptr[i] = e0 + 0;
    for (int i = cur.x + 1; i <= cur.y; i++) g_row_ptr[i] = e0 + 1;
    for (int i = cur.y + 1; i <= cur.z; i++) g_row_ptr[i] = e0 + 2;
    for (int i = cur.z + 1; i <= cur.w; i++) g_row_ptr[i] = e0 + 3;

    if (e0 + 4 == N_EDGES)
        for (int i = cur.w + 1; i <= N_NODES; i++) g_row_ptr[i] = N_EDGES;
}

// ---------------------------------------------------------------------------
// 2) GEMM v9: R12-proven v6 math (tf32 mma.sync m16n8k8, CTA 64x128, BK=16,
// 3-stage cp.async, 4 warps 2(M)x2(N), warp tile 32x64) + airtight tail
// ladder. PDL secondary of wt (grid-sync before g_wt reads) AND PDL primary
// of the rowptr scan (trigger at kernel start so the scan can overlap).
// Epilogue: fp32 C + fp16 shadow.
// ---------------------------------------------------------------------------
#define BM 64
#define BK 16
#define NCH (IN_FEAT / BK)       // 16
#define STAGES 3
#define AP 20
#define BP 136
#define AS_U32 (BM * AP)         // 1280 u32
#define BS_U32 (BK * BP)         // 2176 u32
#define STG_U32 (AS_U32 + BS_U32)             // 3456 u32 = 13824 B
#define SM_TOTAL (STAGES * STG_U32 * 4)       // 41472 B

__global__ void __launch_bounds__(128, 4) gemm_tf32_v9(
    const float* __restrict__ A,   // [M, 256] fp32
    float* __restrict__ C)         // [M, 128] fp32
{
    extern __shared__ uint32_t sm[];
    const uint32_t sb = smem_u32(sm);

    // Release the rowptr scan as early as possible (it depends on nothing here).
    cudaTriggerProgrammaticLaunchCompletion();

    const int tid  = threadIdx.x;
    const int lane = tid & 31;
    const int wid  = tid >> 5;          // 0..3
    const int wm   = wid & 1;
    const int wn   = wid >> 1;
    const int row0 = blockIdx.x * BM;
    const int g    = lane >> 2;
    const int q    = lane & 3;

    float acc[2][8][4];
#pragma unroll
    for (int mi = 0; mi < 2; mi++)
#pragma unroll
        for (int ni = 0; ni < 8; ni++)
#pragma unroll
            for (int j = 0; j < 4; j++) acc[mi][ni][j] = 0.0f;

    const int ar0 = tid >> 2,          ac0 = (tid & 3) * 4;
    const int ar1 = (tid + 128) >> 2,  ac1 = ((tid + 128) & 3) * 4;
    const int asz0 = (row0 + ar0 < N_NODES) ? 16 : 0;
    const int asz1 = (row0 + ar1 < N_NODES) ? 16 : 0;
    const float* asrc0 = A + (size_t)min(row0 + ar0, N_NODES - 1) * IN_FEAT + ac0;
    const float* asrc1 = A + (size_t)min(row0 + ar1, N_NODES - 1) * IN_FEAT + ac1;
    int bk[4], bn[4];
#pragma unroll
    for (int i = 0; i < 4; i++) {
        int idx = tid + i * 128;
        bk[i] = idx >> 5;
        bn[i] = (idx & 31) * 4;
    }

    // Wait for wt_kernel's trigger: g_wt ready after this.
    cudaGridDependencySynchronize();

#define ISSUE(c) do {                                                          \
    const int _st = (c) % STAGES;                                              \
    const int _k0 = (c) * BK;                                                  \
    uint32_t _ab = sb + (_st * STG_U32) * 4;                                   \
    uint32_t _bb = _ab + AS_U32 * 4;                                           \
    cp16z(_ab + (ar0 * AP + ac0) * 4, asrc0 + _k0, asz0);                      \
    cp16z(_ab + (ar1 * AP + ac1) * 4, asrc1 + _k0, asz1);                      \
    _Pragma("unroll")                                                          \
    for (int _i = 0; _i < 4; _i++)                                             \
        cp16(_bb + (bk[_i] * BP + bn[_i]) * 4,                                 \
             g_wt + (_k0 + bk[_i]) * OUT_FEAT + bn[_i]);                       \
    CP_COMMIT();                                                               \
} while (0)

    ISSUE(0);
    ISSUE(1);
    CP_WAIT1();            // stage 0 landed (only groups 0,1 committed)
    __syncthreads();

    for (int c = 0; c < NCH; c++) {
        if (c + 2 < NCH) ISSUE(c + 2);

        const uint32_t* As = sm + (c % STAGES) * STG_U32;
        const uint32_t* Bs = As + AS_U32;

#pragma unroll
        for (int ks = 0; ks < BK; ks += 8) {
            uint32_t af[2][4];
#pragma unroll
            for (int mi = 0; mi < 2; mi++) {
                int m = wm * 32 + mi * 16 + g;
                af[mi][0] = As[m * AP + ks + q];
                af[mi][1] = As[(m + 8) * AP + ks + q];
                af[mi][2] = As[m * AP + ks + q + 4];
                af[mi][3] = As[(m + 8) * AP + ks + q + 4];
            }
            uint32_t bf[8][2];
#pragma unroll
            for (int ni = 0; ni < 8; ni++) {
                int n = wn * 64 + ni * 8 + g;
                bf[ni][0] = Bs[(ks + q) * BP + n];
                bf[ni][1] = Bs[(ks + q + 4) * BP + n];
            }
#pragma unroll
            for (int mi = 0; mi < 2; mi++)
#pragma unroll
                for (int ni = 0; ni < 8; ni++) {
                    asm volatile(
                        "mma.sync.aligned.m16n8k8.row.col.f32.tf32.tf32.f32 "
                        "{%0,%1,%2,%3}, {%4,%5,%6,%7}, {%8,%9}, {%0,%1,%2,%3};"
                        : "+f"(acc[mi][ni][0]), "+f"(acc[mi][ni][1]),
                          "+f"(acc[mi][ni][2]), "+f"(acc[mi][ni][3])
                        : "r"(af[mi][0]), "r"(af[mi][1]), "r"(af[mi][2]), "r"(af[mi][3]),
                          "r"(bf[ni][0]), "r"(bf[ni][1]));
                }
        }

        if (c + 1 < NCH) {
            if (c + 3 <= NCH) CP_WAIT1();   // c <= NCH-3: stage c+1 covered
            else              CP_WAIT0();   // c == NCH-2: last group must drain
            __syncthreads();
        }
    }

    // Epilogue: fp32 to C, fp16 shadow to g_femb16.
#pragma unroll
    for (int mi = 0; mi < 2; mi++) {
        int r1 = row0 + wm * 32 + mi * 16 + g;
        int r2 = r1 + 8;
#pragma unroll
        for (int ni = 0; ni < 8; ni++) {
            int col = wn * 64 + ni * 8 + 2 * q;
            if (r1 < N_NODES) {
                *(float2*)(C + (size_t)r1 * OUT_FEAT + col) =
                    make_float2(acc[mi][ni][0], acc[mi][ni][1]);
                *(__half2*)(g_femb16 + (size_t)r1 * OUT_FEAT + col) =
                    __floats2half2_rn(acc[mi][ni][0], acc[mi][ni][1]);
            }
            if (r2 < N_NODES) {
                *(float2*)(C + (size_t)r2 * OUT_FEAT + col) =
                    make_float2(acc[mi][ni][2], acc[mi][ni][3]);
                *(__half2*)(g_femb16 + (size_t)r2 * OUT_FEAT + col) =
                    __floats2half2_rn(acc[mi][ni][2], acc[mi][ni][3]);
            }
        }
    }
}

// ---------------------------------------------------------------------------
// 4) SpMM (frozen at measured LTS ceiling, ~69.4us): one warp per node; lane
// owns 4 cols (8B fp16 gather), fp32 accumulate; int4/float4 edge loads.
// Normal launch => waits for GEMM and scan via stream order.
// ---------------------------------------------------------------------------
__global__ __launch_bounds__(256) void spmm_kernel(
    const int* __restrict__ edge_col,
    const float* __restrict__ edge_val,
    float* __restrict__ x)
{
    int warp = (blockIdx.x * blockDim.x + threadIdx.x) >> 5;
    if (warp >= N_NODES) return;
    int lane = threadIdx.x & 31;

    int s = g_row_ptr[warp];
    int e = g_row_ptr[warp + 1];

    const __half2* fb = (const __half2*)g_femb16;   // [N * 64] half2

    float4 acc = make_float4(0.f, 0.f, 0.f, 0.f);
    int i = s;

    int head_end = min(e, (s + 3) & ~3);
    for (; i < head_end; i++) {
        int c = __ldg(edge_col + i);
        float v = __ldg(edge_val + i);
        uint2 u = *(const uint2*)(fb + (size_t)c * 64 + lane * 2);
        float2 fa = __half22float2(*(__half2*)&u.x);
        float2 fbv = __half22float2(*(__half2*)&u.y);
        acc.x = fmaf(v, fa.x, acc.x); acc.y = fmaf(v, fa.y, acc.y);
        acc.z = fmaf(v, fbv.x, acc.z); acc.w = fmaf(v, fbv.y, acc.w);
    }

    for (; i + 4 <= e; i += 4) {
        int4   c4 = __ldg((const int4*)(edge_col + i));
        float4 v4 = __ldg((const float4*)(edge_val + i));
        uint2 u0 = *(const uint2*)(fb + (size_t)c4.x * 64 + lane * 2);
        uint2 u1 = *(const uint2*)(fb + (size_t)c4.y * 64 + lane * 2);
        uint2 u2 = *(const uint2*)(fb + (size_t)c4.z * 64 + lane * 2);
        uint2 u3 = *(const uint2*)(fb + (size_t)c4.w * 64 + lane * 2);
        float2 f;
        f = __half22float2(*(__half2*)&u0.x); acc.x = fmaf(v4.x, f.x, acc.x); acc.y = fmaf(v4.x, f.y, acc.y);
        f = __half22float2(*(__half2*)&u0.y); acc.z = fmaf(v4.x, f.x, acc.z); acc.w = fmaf(v4.x, f.y, acc.w);
        f = __half22float2(*(__half2*)&u1.x); acc.x = fmaf(v4.y, f.x, acc.x); acc.y = fmaf(v4.y, f.y, acc.y);
        f = __half22float2(*(__half2*)&u1.y); acc.z = fmaf(v4.y, f.x, acc.z); acc.w = fmaf(v4.y, f.y, acc.w);
        f = __half22float2(*(__half2*)&u2.x); acc.x = fmaf(v4.z, f.x, acc.x); acc.y = fmaf(v4.z, f.y, acc.y);
        f = __half22float2(*(__half2*)&u2.y); acc.z = fmaf(v4.z, f.x, acc.z); acc.w = fmaf(v4.z, f.y, acc.w);
        f = __half22float2(*(__half2*)&u3.x); acc.x = fmaf(v4.w, f.x, acc.x); acc.y = fmaf(v4.w, f.y, acc.y);
        f = __half22float2(*(__half2*)&u3.y); acc.z = fmaf(v4.w, f.x, acc.z); acc.w = fmaf(v4.w, f.y, acc.w);
    }

    for (; i < e; i++) {
        int c = __ldg(edge_col + i);
        float v = __ldg(edge_val + i);
        uint2 u = *(const uint2*)(fb + (size_t)c * 64 + lane * 2);
        float2 fa = __half22float2(*(__half2*)&u.x);
        float2 fbv = __half22float2(*(__half2*)&u.y);
        acc.x = fmaf(v, fa.x, acc.x); acc.y = fmaf(v, fa.y, acc.y);
        acc.z = fmaf(v, fbv.x, acc.z); acc.w = fmaf(v, fbv.y, acc.w);
    }

    *(float4*)(x + (size_t)warp * OUT_FEAT + lane * 4) = acc;
}

// ---------------------------------------------------------------------------
extern "C" void kernel_launch(void* const* d_in, const int* in_sizes, int n_in,
                              void* d_out, int out_size)
{
    const float* feat     = (const float*)d_in[0];
    const int*   edge_row = (const int*)d_in[1];
    const int*   edge_col = (const int*)d_in[2];
    const float* edge_val = (const float*)d_in[3];
    const float* weight   = (const float*)d_in[4];

    float* femb = (float*)d_out;                              // [N, 128]
    float* x    = (float*)d_out + (size_t)N_NODES * OUT_FEAT; // [N, 128]

    cudaFuncSetAttribute(gemm_tf32_v9, cudaFuncAttributeMaxDynamicSharedMemorySize, SM_TOTAL);

    // 1) wt convert — single wave, trigger fires early.
    wt_kernel<<<(IN_FEAT * OUT_FEAT + 127) / 128, 128>>>(weight);

    // 2) GEMM — PDL secondary of wt (launches during wt, syncs before g_wt reads).
    {
        cudaLaunchConfig_t cfg = {};
        cfg.gridDim = dim3((N_NODES + BM - 1) / BM);   // 1563
        cfg.blockDim = dim3(128);
        cfg.dynamicSmemBytes = SM_TOTAL;
        cfg.stream = 0;
        cudaLaunchAttribute attr[1];
        attr[0].id = cudaLaunchAttributeProgrammaticStreamSerialization;
        attr[0].val.programmaticStreamSerializationAllowed = 1;
        cfg.attrs = attr;
        cfg.numAttrs = 1;
        cudaLaunchKernelEx(&cfg, gemm_tf32_v9, feat, femb);
    }

    // 3) rowptr scan — PDL secondary of the GEMM; no data dependency on it,
    // so it overlaps the GEMM's tail.
    {
        cudaLaunchConfig_t cfg = {};
        cfg.gridDim = dim3((N_EDGES / 4 + 255) / 256); // 3125
        cfg.blockDim = dim3(256);
        cfg.dynamicSmemBytes = 0;
        cfg.stream = 0;
        cudaLaunchAttribute attr[1];
        attr[0].id = cudaLaunchAttributeProgrammaticStreamSerialization;
        attr[0].val.programmaticStreamSerializationAllowed = 1;
        cfg.attrs = attr;
        cfg.numAttrs = 1;
        cudaLaunchKernelEx(&cfg, rowptr_kernel, edge_row);
    }

    // 4) SpMM — normal launch; stream order guarantees GEMM + scan complete.
    int spmm_blocks = (N_NODES + 7) / 8;
    spmm_kernel<<<spmm_blocks, 256>>>(edge_col, edge_val, x);
}